// round 3
// baseline (speedup 1.0000x reference)
#include <cuda_runtime.h>
#include <cuda_bf16.h>
#include <mma.h>

using namespace nvcuda;

// Problem shapes (fixed by setup_inputs)
#define N_WORLDS 2048
#define DIM      64
#define N_W      512
#define BATCH    1024
#define MAXC     64          // max contributions per output row (actual max ~10 w.h.p.)

#define WT       128         // worlds per CTA tile
#define NTILES   (N_WORLDS / WT)   // 16
#define THREADS  256

// smem pitches (floats)
#define PAD_B    72          // pitch for worlds tile and A tile (mult of 4)
#define PAD_Y    132         // pitch for Y tile (mult of 4; column reads conflict-free)

#define SWT_OFF  0                            // [128][72] = 9216
#define SA_OFF   (WT * PAD_B)                 // 9216, [64][72] = 4608
#define SY_OFF   (SA_OFF + DIM * PAD_B)       // 13824, [64][132] = 8448
#define SSC_OFF  (SY_OFF + DIM * PAD_Y)       // 22272, [128]
#define SMEM_FLOATS (SSC_OFF + WT)            // 22400
#define SMEM_BYTES  (SMEM_FLOATS * 4)         // 89600

// Scratch for row -> contribution lists (device globals: no allocation allowed)
__device__ int g_cnt[BATCH];
__device__ unsigned int g_lst[BATCH * MAXC];

// Round f32 -> tf32 in place. PTX cvt.rna.tf32.f32 has a .b32 destination, so
// the output constraint must be "=r" (b32 reg), not "=f". Idempotent.
__device__ __forceinline__ float to_tf32(float x) {
    unsigned int y;
    asm("cvt.rna.tf32.f32 %0, %1;\n" : "=r"(y) : "f"(x));
    return __uint_as_float(y);
}

// ---------------------------------------------------------------------------
// Kernel 1: bin samples by output row. Deterministic: atomic placement is
// followed by an insertion sort on the (n<<16)|j keys, so list order (and thus
// float summation order) is identical on every replay.
// ---------------------------------------------------------------------------
__global__ void bin_kernel(const int* __restrict__ nullary) {
    int tid = threadIdx.x;   // one CTA of 1024 threads
    g_cnt[tid] = 0;
    __syncthreads();

    int r = nullary[2 * tid + 0];
    int j = nullary[2 * tid + 1];
    int pos = atomicAdd(&g_cnt[r], 1);
    if (pos < MAXC)
        g_lst[r * MAXC + pos] = ((unsigned)tid << 16) | (unsigned)j;
    __syncthreads();

    int c = g_cnt[tid];
    if (c > MAXC) c = MAXC;
    unsigned* L = &g_lst[tid * MAXC];
    for (int a = 1; a < c; a++) {
        unsigned v = L[a];
        int b = a - 1;
        while (b >= 0 && L[b] > v) { L[b + 1] = L[b]; b--; }
        L[b + 1] = v;
    }
}

// ---------------------------------------------------------------------------
// Kernel 2: one CTA per (output row, 128-world tile).
//   For each contributing sample j: Y[64 x 128] = W[j] (64x64) @ worldsT via
//   WMMA tf32; column-L2-normalize Y; accumulate into register tile; write
//   the output tile exactly once (zero-count rows: pure zero-fill fast path).
// ---------------------------------------------------------------------------
extern __shared__ float smem[];

__global__ void __launch_bounds__(THREADS)
nullary_kernel(const float* __restrict__ worlds,
               const float* __restrict__ W,
               float* __restrict__ out) {
    float* sWt = smem + SWT_OFF;   // worlds tile [w][e], pitch PAD_B (tf32-rounded)
    float* sA  = smem + SA_OFF;    // W[j]       [d][e], pitch PAD_B (tf32-rounded)
    float* sY  = smem + SY_OFF;    // Y          [d][w], pitch PAD_Y
    float* sSc = smem + SSC_OFF;   // per-column scale [WT]

    const int tid = threadIdx.x;
    const int r   = blockIdx.y;
    const int w0  = blockIdx.x * WT;
    float* outp = out + (size_t)r * (DIM * N_WORLDS) + w0;

    int c = g_cnt[r];
    if (c > MAXC) c = MAXC;

    if (c == 0) {
        // zero-fill fast path: 64 rows x 128 cols, float4, coalesced, streaming
        float4 z = make_float4(0.f, 0.f, 0.f, 0.f);
        #pragma unroll
        for (int i = tid; i < DIM * WT / 4; i += THREADS) {
            int d = i >> 5, q = i & 31;
            __stcs((float4*)(outp + (size_t)d * N_WORLDS + q * 4), z);
        }
        return;
    }

    // Load worlds tile into smem, rounding to tf32 once: [w][e], pitch PAD_B
    {
        const float4* g = (const float4*)(worlds + (size_t)w0 * DIM);
        #pragma unroll
        for (int i = tid; i < WT * (DIM / 4); i += THREADS) {
            int w = i >> 4, e4 = i & 15;
            float4 v = __ldg(&g[i]);
            v.x = to_tf32(v.x); v.y = to_tf32(v.y);
            v.z = to_tf32(v.z); v.w = to_tf32(v.w);
            *(float4*)&sWt[w * PAD_B + e4 * 4] = v;
        }
    }

    // Register accumulator: 8 float4 per thread covers the full 64x128 tile.
    // idx4 = tid + 256*k4 ; d = idx4>>5 ; q = idx4&31 (float4 column group)
    float4 ACC[8];
    #pragma unroll
    for (int k = 0; k < 8; k++) ACC[k] = make_float4(0.f, 0.f, 0.f, 0.f);

    const int wid    = tid >> 5;
    const int warp_d = wid >> 1;   // 0..3 -> d rows [warp_d*16, +16)
    const int warp_w = wid & 1;    // 0..1 -> w cols [warp_w*64, +64)

    for (int ci = 0; ci < c; ci++) {
        const int j = (int)(g_lst[r * MAXC + ci] & 0xFFFFu);

        // Load A = W[j] (64x64) into smem, tf32-rounded (L2-resident, coalesced)
        {
            const float4* gA = (const float4*)(W + (size_t)j * (DIM * DIM));
            #pragma unroll
            for (int i = tid; i < DIM * (DIM / 4); i += THREADS) {
                int row = i >> 4, c4 = i & 15;
                float4 v = __ldg(&gA[i]);
                v.x = to_tf32(v.x); v.y = to_tf32(v.y);
                v.z = to_tf32(v.z); v.w = to_tf32(v.w);
                *(float4*)&sA[row * PAD_B + c4 * 4] = v;
            }
        }
        __syncthreads();   // B0: sA ready; also orders prev-iter sY reads vs new stores

        // Y = A @ worldsT  via tf32 WMMA (m16n16k8), per-warp 16(d) x 64(w)
        wmma::fragment<wmma::accumulator, 16, 16, 8, float> acc[4];
        #pragma unroll
        for (int f = 0; f < 4; f++) wmma::fill_fragment(acc[f], 0.0f);

        #pragma unroll
        for (int kk = 0; kk < DIM; kk += 8) {
            wmma::fragment<wmma::matrix_a, 16, 16, 8, wmma::precision::tf32,
                           wmma::row_major> fa;
            wmma::load_matrix_sync(fa, &sA[(warp_d * 16) * PAD_B + kk], PAD_B);
            #pragma unroll
            for (int f = 0; f < 4; f++) {
                wmma::fragment<wmma::matrix_b, 16, 16, 8, wmma::precision::tf32,
                               wmma::col_major> fb;
                wmma::load_matrix_sync(
                    fb, &sWt[(warp_w * 64 + f * 16) * PAD_B + kk], PAD_B);
                wmma::mma_sync(acc[f], fa, fb, acc[f]);
            }
        }
        #pragma unroll
        for (int f = 0; f < 4; f++)
            wmma::store_matrix_sync(
                &sY[(warp_d * 16) * PAD_Y + warp_w * 64 + f * 16],
                acc[f], PAD_Y, wmma::mem_row_major);
        __syncthreads();   // B1: full Y visible

        // Column L2 scale: thread t (<128) owns column t; reads are conflict-free
        if (tid < WT) {
            float sq = 0.f;
            #pragma unroll 8
            for (int d = 0; d < DIM; d++) {
                float v = sY[d * PAD_Y + tid];
                sq += v * v;
            }
            sSc[tid] = rsqrtf(fmaxf(sq, 1e-12f));
        }
        __syncthreads();   // B2: scales visible

        // ACC += Y * scale  (float4 smem reads, conflict-free)
        #pragma unroll
        for (int k4 = 0; k4 < 8; k4++) {
            int idx4 = tid + THREADS * k4;
            int d = idx4 >> 5, q = idx4 & 31;
            float4 y = *(float4*)&sY[d * PAD_Y + q * 4];
            float4 s = *(float4*)&sSc[q * 4];
            ACC[k4].x += y.x * s.x;
            ACC[k4].y += y.y * s.y;
            ACC[k4].z += y.z * s.z;
            ACC[k4].w += y.w * s.w;
        }
    }

    // Single coalesced streaming float4 write of the whole tile
    #pragma unroll
    for (int k4 = 0; k4 < 8; k4++) {
        int idx4 = tid + THREADS * k4;
        int d = idx4 >> 5, q = idx4 & 31;
        __stcs((float4*)(outp + (size_t)d * N_WORLDS + q * 4), ACC[k4]);
    }
}

// ---------------------------------------------------------------------------
extern "C" void kernel_launch(void* const* d_in, const int* in_sizes, int n_in,
                              void* d_out, int out_size) {
    (void)in_sizes; (void)n_in; (void)out_size;
    const float* worlds  = (const float*)d_in[0];   // (2048, 64) f32
    const float* W       = (const float*)d_in[1];   // (512, 64, 64) f32
    const int*   nullary = (const int*)d_in[2];     // (1024, 2) i32
    float*       out     = (float*)d_out;           // (1024, 64, 2048) f32

    cudaFuncSetAttribute(nullary_kernel,
                         cudaFuncAttributeMaxDynamicSharedMemorySize,
                         SMEM_BYTES);

    bin_kernel<<<1, BATCH>>>(nullary);
    nullary_kernel<<<dim3(NTILES, BATCH), THREADS, SMEM_BYTES>>>(worlds, W, out);
}

// round 4
// speedup vs baseline: 1.9442x; 1.9442x over previous
#include <cuda_runtime.h>

// Problem shapes (fixed by setup_inputs)
#define N_WORLDS 2048
#define DIM      64
#define BATCH    1024
#define MAXC     64          // max contributions per output row (actual max ~10 w.h.p.)

#define WT       128         // worlds per CTA tile
#define NTILES   (N_WORLDS / WT)   // 16
#define THREADS  256

// smem pitches (floats)
#define PW       68          // pitch for worlds tile and W tile (conflict-free frag LDS)
#define PY       132         // pitch for transpose buffer

// smem layout (floats). Worlds tile is only read in the prologue (A-frags are
// register-resident), so the epilogue transpose buffer sY UNIONs with it.
#define WORLDS_OFF 0                        // [128][68] = 8704
#define SY_OFF     0                        // [64][132] = 8448 (aliases worlds)
#define WS_OFF     (WT * PW)                // 8704, W[j] tile [64][68] = 4352
#define SMEM_FLOATS (WS_OFF + DIM * PW)     // 13056
#define SMEM_BYTES  (SMEM_FLOATS * 4)       // 52224

// Scratch for row -> contribution lists (device globals: no allocation allowed)
__device__ int g_cnt[BATCH];
__device__ unsigned int g_lst[BATCH * MAXC];

// Round f32 -> tf32 (b32 destination => "=r" constraint). Idempotent.
__device__ __forceinline__ float to_tf32(float x) {
    unsigned int y;
    asm("cvt.rna.tf32.f32 %0, %1;\n" : "=r"(y) : "f"(x));
    return __uint_as_float(y);
}

__device__ __forceinline__ void mma_tf32(
    float& d0, float& d1, float& d2, float& d3,
    unsigned a0, unsigned a1, unsigned a2, unsigned a3,
    unsigned b0, unsigned b1,
    float c0, float c1, float c2, float c3)
{
    asm volatile(
        "mma.sync.aligned.m16n8k8.row.col.f32.tf32.tf32.f32 "
        "{%0,%1,%2,%3}, {%4,%5,%6,%7}, {%8,%9}, {%10,%11,%12,%13};\n"
        : "=f"(d0), "=f"(d1), "=f"(d2), "=f"(d3)
        : "r"(a0), "r"(a1), "r"(a2), "r"(a3), "r"(b0), "r"(b1),
          "f"(c0), "f"(c1), "f"(c2), "f"(c3));
}

// ---------------------------------------------------------------------------
// Kernel 1: bin samples by output row. Deterministic: atomic placement is
// followed by an insertion sort on the (n<<16)|j keys, so list order (and thus
// float summation order) is identical on every replay.
// ---------------------------------------------------------------------------
__global__ void bin_kernel(const int* __restrict__ nullary) {
    int tid = threadIdx.x;   // one CTA of 1024 threads
    g_cnt[tid] = 0;
    __syncthreads();

    int r = nullary[2 * tid + 0];
    int j = nullary[2 * tid + 1];
    int pos = atomicAdd(&g_cnt[r], 1);
    if (pos < MAXC)
        g_lst[r * MAXC + pos] = ((unsigned)tid << 16) | (unsigned)j;
    __syncthreads();

    int c = g_cnt[tid];
    if (c > MAXC) c = MAXC;
    unsigned* L = &g_lst[tid * MAXC];
    for (int a = 1; a < c; a++) {
        unsigned v = L[a];
        int b = a - 1;
        while (b >= 0 && L[b] > v) { L[b + 1] = L[b]; b--; }
        L[b + 1] = v;
    }
}

// ---------------------------------------------------------------------------
// Kernel 2: one CTA per (output row, 128-world tile).
// Computes Y^T (worlds x d) = worlds_tile @ W[j]^T via raw mma.sync tf32 with
// register-resident A (worlds) fragments and register-resident Y/ACC.
// Per-sample L2 norm over d = per-row (m) reduction: thread partials + 2x
// shfl.bfly within the quad. One smem transpose at the end, then coalesced
// streaming float4 stores. Zero-count rows: pure zero-fill fast path.
// ---------------------------------------------------------------------------
extern __shared__ float smem[];

__global__ void __launch_bounds__(THREADS, 2)
nullary_kernel(const float* __restrict__ worlds,
               const float* __restrict__ W,
               float* __restrict__ out) {
    const int tid  = threadIdx.x;
    const int warp = tid >> 5;
    const int lane = tid & 31;
    const int g    = lane >> 2;   // groupID (0..7)
    const int tg   = lane & 3;    // thread-in-group (0..3)

    const int r  = blockIdx.y;
    const int w0 = blockIdx.x * WT;
    float* outp = out + (size_t)r * (DIM * N_WORLDS) + w0;

    int c = g_cnt[r];
    if (c > MAXC) c = MAXC;

    if (c == 0) {
        // zero-fill fast path: 64 rows x 128 cols, float4, coalesced, streaming
        float4 z = make_float4(0.f, 0.f, 0.f, 0.f);
        #pragma unroll
        for (int i = tid; i < DIM * WT / 4; i += THREADS) {
            int d = i >> 5, q = i & 31;
            __stcs((float4*)(outp + (size_t)d * N_WORLDS + q * 4), z);
        }
        return;
    }

    float* sWor = smem + WORLDS_OFF;
    float* sW   = smem + WS_OFF;
    float* sY   = smem + SY_OFF;

    // Prologue: stage worlds tile (tf32-rounded) [w][e], pitch PW
    {
        const float4* gw = (const float4*)(worlds + (size_t)w0 * DIM);
        #pragma unroll
        for (int i = tid; i < WT * (DIM / 4); i += THREADS) {
            int w = i >> 4, e4 = i & 15;
            float4 v = __ldg(&gw[i]);
            v.x = to_tf32(v.x); v.y = to_tf32(v.y);
            v.z = to_tf32(v.z); v.w = to_tf32(v.w);
            *(float4*)&sWor[w * PW + e4 * 4] = v;
        }
    }
    __syncthreads();

    // A fragments (worlds rows), loop-invariant, register-resident.
    // m16n8k8 A map: a0(row=g,col=tg) a1(row=g+8,col=tg) a2(row=g,col=tg+4) a3(row=g+8,col=tg+4)
    unsigned A0[8], A1[8], A2[8], A3[8];
    {
        const int row0 = (warp * 16 + g) * PW;
        const int row1 = (warp * 16 + 8 + g) * PW;
        #pragma unroll
        for (int ks = 0; ks < 8; ks++) {
            A0[ks] = __float_as_uint(sWor[row0 + tg     + 8 * ks]);
            A2[ks] = __float_as_uint(sWor[row0 + tg + 4 + 8 * ks]);
            A1[ks] = __float_as_uint(sWor[row1 + tg     + 8 * ks]);
            A3[ks] = __float_as_uint(sWor[row1 + tg + 4 + 8 * ks]);
        }
    }

    float ACC[32];
    #pragma unroll
    for (int k = 0; k < 32; k++) ACC[k] = 0.f;

    for (int ci = 0; ci < c; ci++) {
        const int j = (int)(g_lst[r * MAXC + ci] & 0xFFFFu);

        // Stage W[j] [d][e] (tf32-rounded) into smem, pitch PW. L2-resident.
        {
            const float4* gA = (const float4*)(W + (size_t)j * (DIM * DIM));
            #pragma unroll
            for (int i = tid; i < DIM * (DIM / 4); i += THREADS) {
                int row = i >> 4, c4 = i & 15;
                float4 v = __ldg(&gA[i]);
                v.x = to_tf32(v.x); v.y = to_tf32(v.y);
                v.z = to_tf32(v.z); v.w = to_tf32(v.w);
                *(float4*)&sW[row * PW + c4 * 4] = v;
            }
        }
        __syncthreads();   // sW ready

        // Y^T[16w x 64d] per warp, fully in registers.
        float Y[32];
        #pragma unroll
        for (int k = 0; k < 32; k++) Y[k] = 0.f;

        // B (W[j]^T): B[k=e][n=d] = sW[d*PW + e].
        // m16n8k8 B map: b0(row=tg,col=g), b1(row=tg+4,col=g)
        #pragma unroll
        for (int ks = 0; ks < 8; ks++) {
            #pragma unroll
            for (int nt = 0; nt < 8; nt++) {
                unsigned b0 = __float_as_uint(sW[(nt * 8 + g) * PW + tg     + 8 * ks]);
                unsigned b1 = __float_as_uint(sW[(nt * 8 + g) * PW + tg + 4 + 8 * ks]);
                mma_tf32(Y[4*nt], Y[4*nt+1], Y[4*nt+2], Y[4*nt+3],
                         A0[ks], A1[ks], A2[ks], A3[ks], b0, b1,
                         Y[4*nt], Y[4*nt+1], Y[4*nt+2], Y[4*nt+3]);
            }
        }

        // Per-world L2 norm over d (= the n dimension, full row per quad).
        // c0,c1 belong to world-row g; c2,c3 to world-row g+8.
        float s0 = 0.f, s1 = 0.f;
        #pragma unroll
        for (int nt = 0; nt < 8; nt++) {
            s0 += Y[4*nt]   * Y[4*nt]   + Y[4*nt+1] * Y[4*nt+1];
            s1 += Y[4*nt+2] * Y[4*nt+2] + Y[4*nt+3] * Y[4*nt+3];
        }
        s0 += __shfl_xor_sync(0xFFFFFFFFu, s0, 1);
        s0 += __shfl_xor_sync(0xFFFFFFFFu, s0, 2);
        s1 += __shfl_xor_sync(0xFFFFFFFFu, s1, 1);
        s1 += __shfl_xor_sync(0xFFFFFFFFu, s1, 2);
        const float sc0 = rsqrtf(fmaxf(s0, 1e-12f));
        const float sc1 = rsqrtf(fmaxf(s1, 1e-12f));

        #pragma unroll
        for (int nt = 0; nt < 8; nt++) {
            ACC[4*nt]   += Y[4*nt]   * sc0;
            ACC[4*nt+1] += Y[4*nt+1] * sc0;
            ACC[4*nt+2] += Y[4*nt+2] * sc1;
            ACC[4*nt+3] += Y[4*nt+3] * sc1;
        }
        __syncthreads();   // protect sW against next iteration's staging
    }

    // Epilogue: transpose ACC (w-major frags) -> sY [d][w], then coalesced
    // streaming stores. sY aliases the worlds tile (dead after A-frag load).
    #pragma unroll
    for (int nt = 0; nt < 8; nt++) {
        const int d0  = nt * 8 + 2 * tg;
        const int wl  = warp * 16 + g;
        sY[d0       * PY + wl]     = ACC[4*nt];
        sY[(d0 + 1) * PY + wl]     = ACC[4*nt+1];
        sY[d0       * PY + wl + 8] = ACC[4*nt+2];
        sY[(d0 + 1) * PY + wl + 8] = ACC[4*nt+3];
    }
    __syncthreads();

    #pragma unroll
    for (int k4 = 0; k4 < 8; k4++) {
        int idx4 = tid + THREADS * k4;
        int d = idx4 >> 5, q = idx4 & 31;
        float4 v = *(float4*)&sY[d * PY + q * 4];
        __stcs((float4*)(outp + (size_t)d * N_WORLDS + q * 4), v);
    }
}

// ---------------------------------------------------------------------------
extern "C" void kernel_launch(void* const* d_in, const int* in_sizes, int n_in,
                              void* d_out, int out_size) {
    (void)in_sizes; (void)n_in; (void)out_size;
    const float* worlds  = (const float*)d_in[0];   // (2048, 64) f32
    const float* W       = (const float*)d_in[1];   // (512, 64, 64) f32
    const int*   nullary = (const int*)d_in[2];     // (1024, 2) i32
    float*       out     = (float*)d_out;           // (1024, 64, 2048) f32

    cudaFuncSetAttribute(nullary_kernel,
                         cudaFuncAttributeMaxDynamicSharedMemorySize,
                         SMEM_BYTES);

    bin_kernel<<<1, BATCH>>>(nullary);
    nullary_kernel<<<dim3(NTILES, BATCH), THREADS, SMEM_BYTES>>>(worlds, W, out);
}

// round 7
// speedup vs baseline: 2.0990x; 1.0797x over previous
#include <cuda_runtime.h>

// Problem shapes (fixed by setup_inputs)
#define N_WORLDS 2048
#define DIM      64
#define BATCH    1024
#define MAXC     64          // max contributions per output row (actual max ~10 w.h.p.)

#define WT       128         // worlds per CTA tile
#define NTILES   (N_WORLDS / WT)   // 16
#define THREADS  256

// smem pitches (floats)
#define PW       68          // pitch for worlds + W tiles (conflict-free LDS/LDSM)
#define PY       132         // pitch for epilogue transpose buffer

// smem layout (floats). Worlds tile is only read in the prologue (A-frags are
// register-resident), so the epilogue transpose buffer sY UNIONs with it.
// W[j] is double-buffered for cp.async pipelining.
#define WORLDS_OFF 0                        // [128][68] = 8704
#define SY_OFF     0                        // [64][132] = 8448 (aliases worlds)
#define WS_OFF     (WT * PW)                // 8704
#define WS_BUF     (DIM * PW)               // 4352 floats per buffer
#define SMEM_FLOATS (WS_OFF + 2 * WS_BUF)   // 17408
#define SMEM_BYTES  (SMEM_FLOATS * 4)       // 69632

// Scratch for row -> contribution lists (device globals: no allocation allowed)
__device__ int g_cnt[BATCH];
__device__ unsigned int g_lst[BATCH * MAXC];

// Round f32 -> tf32 (b32 destination => "=r" constraint). Idempotent.
__device__ __forceinline__ float to_tf32(float x) {
    unsigned int y;
    asm("cvt.rna.tf32.f32 %0, %1;\n" : "=r"(y) : "f"(x));
    return __uint_as_float(y);
}

__device__ __forceinline__ void mma_tf32(
    float& d0, float& d1, float& d2, float& d3,
    unsigned a0, unsigned a1, unsigned a2, unsigned a3,
    unsigned b0, unsigned b1)
{
    asm volatile(
        "mma.sync.aligned.m16n8k8.row.col.f32.tf32.tf32.f32 "
        "{%0,%1,%2,%3}, {%4,%5,%6,%7}, {%8,%9}, {%0,%1,%2,%3};\n"
        : "+f"(d0), "+f"(d1), "+f"(d2), "+f"(d3)
        : "r"(a0), "r"(a1), "r"(a2), "r"(a3), "r"(b0), "r"(b1));
}

// ---------------------------------------------------------------------------
// Kernel 1: bin samples by output row. Deterministic: atomic placement is
// followed by an insertion sort on the (n<<16)|j keys, so list order (and thus
// float summation order) is identical on every replay.
// ---------------------------------------------------------------------------
__global__ void bin_kernel(const int* __restrict__ nullary) {
    int tid = threadIdx.x;   // one CTA of 1024 threads
    g_cnt[tid] = 0;
    __syncthreads();

    int r = nullary[2 * tid + 0];
    int j = nullary[2 * tid + 1];
    int pos = atomicAdd(&g_cnt[r], 1);
    if (pos < MAXC)
        g_lst[r * MAXC + pos] = ((unsigned)tid << 16) | (unsigned)j;
    __syncthreads();

    int c = g_cnt[tid];
    if (c > MAXC) c = MAXC;
    unsigned* L = &g_lst[tid * MAXC];
    for (int a = 1; a < c; a++) {
        unsigned v = L[a];
        int b = a - 1;
        while (b >= 0 && L[b] > v) { L[b + 1] = L[b]; b--; }
        L[b + 1] = v;
    }
}

// ---------------------------------------------------------------------------
// Kernel 2: one CTA per (output row, 128-world tile).
// Y^T (worlds x d) = worlds_tile @ W[j]^T via mma.sync tf32:
//   A (worlds) fragments register-resident and loop-invariant,
//   B fragments via ldmatrix.x4 (b16 half-tile trick for f32 data),
//   W[j] staged with cp.async.cg into a double buffer (overlaps with MMA;
//     tf32 mma truncates the raw f32 low mantissa bits, so no cvt needed),
//   per-sample L2 norm over d via quad shfl reduction (no smem),
//   one smem transpose at the end, coalesced streaming float4 stores.
// Zero-count rows take a pure zero-fill fast path.
// ---------------------------------------------------------------------------
extern __shared__ float smem[];

__global__ void __launch_bounds__(THREADS, 2)
nullary_kernel(const float* __restrict__ worlds,
               const float* __restrict__ W,
               float* __restrict__ out) {
    const int tid  = threadIdx.x;
    const int warp = tid >> 5;
    const int lane = tid & 31;
    const int g    = lane >> 2;   // groupID (0..7)
    const int tg   = lane & 3;    // thread-in-group (0..3)

    const int r  = blockIdx.y;
    const int w0 = blockIdx.x * WT;
    float* outp = out + (size_t)r * (DIM * N_WORLDS) + w0;

    int c = g_cnt[r];
    if (c > MAXC) c = MAXC;

    if (c == 0) {
        // zero-fill fast path: 64 rows x 128 cols, float4, coalesced, streaming
        float4 z = make_float4(0.f, 0.f, 0.f, 0.f);
        #pragma unroll
        for (int i = tid; i < DIM * WT / 4; i += THREADS) {
            int d = i >> 5, q = i & 31;
            __stcs((float4*)(outp + (size_t)d * N_WORLDS + q * 4), z);
        }
        return;
    }

    float* sWor = smem + WORLDS_OFF;
    float* sY   = smem + SY_OFF;
    const unsigned sbase = (unsigned)__cvta_generic_to_shared(smem);

    // Prologue: stage worlds tile (tf32-rounded) [w][e], pitch PW
    {
        const float4* gw = (const float4*)(worlds + (size_t)w0 * DIM);
        #pragma unroll
        for (int i = tid; i < WT * (DIM / 4); i += THREADS) {
            int w = i >> 4, e4 = i & 15;
            float4 v = __ldg(&gw[i]);
            v.x = to_tf32(v.x); v.y = to_tf32(v.y);
            v.z = to_tf32(v.z); v.w = to_tf32(v.w);
            *(float4*)&sWor[w * PW + e4 * 4] = v;
        }
    }

    // Prefetch W[j0] into buffer 0 with cp.async.cg (16B chunks, coalesced src,
    // L1-bypass: data is consumed from smem, keep L1 clean).
    const unsigned* lst = &g_lst[r * MAXC];
    {
        const int j0 = (int)(lst[0] & 0xFFFFu);
        const float4* src = (const float4*)(W + (size_t)j0 * (DIM * DIM));
        const unsigned dbase = sbase + (unsigned)(WS_OFF * 4);
        #pragma unroll
        for (int k = 0; k < 4; k++) {
            int i = tid + THREADS * k;
            unsigned dst = dbase + (unsigned)(((i >> 4) * PW + (i & 15) * 4) * 4);
            asm volatile("cp.async.cg.shared.global [%0], [%1], 16;\n"
                         :: "r"(dst), "l"(src + i) : "memory");
        }
        asm volatile("cp.async.commit_group;\n" ::: "memory");
    }
    __syncthreads();   // worlds tile visible

    // A fragments (worlds rows), loop-invariant, register-resident.
    // m16n8k8 A map: a0(row=g,col=tg) a1(row=g+8,col=tg) a2(row=g,col=tg+4) a3(row=g+8,col=tg+4)
    unsigned A0[8], A1[8], A2[8], A3[8];
    {
        const int row0 = (warp * 16 + g) * PW;
        const int row1 = (warp * 16 + 8 + g) * PW;
        #pragma unroll
        for (int ks = 0; ks < 8; ks++) {
            A0[ks] = __float_as_uint(sWor[row0 + tg     + 8 * ks]);
            A2[ks] = __float_as_uint(sWor[row0 + tg + 4 + 8 * ks]);
            A1[ks] = __float_as_uint(sWor[row1 + tg     + 8 * ks]);
            A3[ks] = __float_as_uint(sWor[row1 + tg + 4 + 8 * ks]);
        }
    }

    float ACC[32];
    #pragma unroll
    for (int k = 0; k < 32; k++) ACC[k] = 0.f;

    // ldmatrix lane-constant address part. Lanes are split into 4 groups of 8:
    //   sub=0: b0 of ks even  (row base + 0B)
    //   sub=1: b1 of ks even  (+16B)
    //   sub=2: b0 of ks odd   (+32B)
    //   sub=3: b1 of ks odd   (+48B)
    const int lrow = lane & 7;
    const int sub  = lane >> 3;
    const unsigned lane_off = (unsigned)(((sub & 1) * 16) + ((sub >> 1) * 32)
                                         + lrow * PW * 4);

    for (int ci = 0; ci < c; ci++) {
        asm volatile("cp.async.wait_group 0;\n" ::: "memory");
        __syncthreads();   // buf[ci&1] ready; all prior reads of buf[(ci+1)&1] closed

        if (ci + 1 < c) {
            const int jn = (int)(lst[ci + 1] & 0xFFFFu);
            const float4* src = (const float4*)(W + (size_t)jn * (DIM * DIM));
            const unsigned dbase = sbase
                + (unsigned)((WS_OFF + ((ci + 1) & 1) * WS_BUF) * 4);
            #pragma unroll
            for (int k = 0; k < 4; k++) {
                int i = tid + THREADS * k;
                unsigned dst = dbase + (unsigned)(((i >> 4) * PW + (i & 15) * 4) * 4);
                asm volatile("cp.async.cg.shared.global [%0], [%1], 16;\n"
                             :: "r"(dst), "l"(src + i) : "memory");
            }
            asm volatile("cp.async.commit_group;\n" ::: "memory");
        }

        const unsigned wbase = sbase
            + (unsigned)((WS_OFF + (ci & 1) * WS_BUF) * 4) + lane_off;

        // Y^T[16w x 64d] per warp, fully in registers.
        float Y[32];
        #pragma unroll
        for (int k = 0; k < 32; k++) Y[k] = 0.f;

        #pragma unroll
        for (int nt = 0; nt < 8; nt++) {
            const unsigned abase = wbase + (unsigned)(nt * 8 * PW * 4);
            #pragma unroll
            for (int kp = 0; kp < 4; kp++) {
                unsigned b00, b01, b10, b11;   // (b0,b1) for ks=2kp and ks=2kp+1
                asm volatile(
                    "ldmatrix.sync.aligned.m8n8.x4.shared.b16 {%0,%1,%2,%3}, [%4];\n"
                    : "=r"(b00), "=r"(b01), "=r"(b10), "=r"(b11)
                    : "r"(abase + (unsigned)(kp * 64)));
                mma_tf32(Y[4*nt], Y[4*nt+1], Y[4*nt+2], Y[4*nt+3],
                         A0[2*kp],   A1[2*kp],   A2[2*kp],   A3[2*kp],   b00, b01);
                mma_tf32(Y[4*nt], Y[4*nt+1], Y[4*nt+2], Y[4*nt+3],
                         A0[2*kp+1], A1[2*kp+1], A2[2*kp+1], A3[2*kp+1], b10, b11);
            }
        }

        // Per-world L2 norm over d (= the n dimension, full row per quad).
        float s0 = 0.f, s1 = 0.f;
        #pragma unroll
        for (int nt = 0; nt < 8; nt++) {
            s0 += Y[4*nt]   * Y[4*nt]   + Y[4*nt+1] * Y[4*nt+1];
            s1 += Y[4*nt+2] * Y[4*nt+2] + Y[4*nt+3] * Y[4*nt+3];
        }
        s0 += __shfl_xor_sync(0xFFFFFFFFu, s0, 1);
        s0 += __shfl_xor_sync(0xFFFFFFFFu, s0, 2);
        s1 += __shfl_xor_sync(0xFFFFFFFFu, s1, 1);
        s1 += __shfl_xor_sync(0xFFFFFFFFu, s1, 2);
        const float sc0 = rsqrtf(fmaxf(s0, 1e-12f));
        const float sc1 = rsqrtf(fmaxf(s1, 1e-12f));

        #pragma unroll
        for (int nt = 0; nt < 8; nt++) {
            ACC[4*nt]   += Y[4*nt]   * sc0;
            ACC[4*nt+1] += Y[4*nt+1] * sc0;
            ACC[4*nt+2] += Y[4*nt+2] * sc1;
            ACC[4*nt+3] += Y[4*nt+3] * sc1;
        }
    }

    // Epilogue: transpose ACC (w-major frags) -> sY [d][w], then coalesced
    // streaming stores. sY aliases the worlds tile (dead after A-frag load).
    #pragma unroll
    for (int nt = 0; nt < 8; nt++) {
        const int d0 = nt * 8 + 2 * tg;
        const int wl = warp * 16 + g;
        sY[d0       * PY + wl]     = ACC[4*nt];
        sY[(d0 + 1) * PY + wl]     = ACC[4*nt+1];
        sY[d0       * PY + wl + 8] = ACC[4*nt+2];
        sY[(d0 + 1) * PY + wl + 8] = ACC[4*nt+3];
    }
    __syncthreads();

    #pragma unroll
    for (int k4 = 0; k4 < 8; k4++) {
        int idx4 = tid + THREADS * k4;
        int d = idx4 >> 5, q = idx4 & 31;
        float4 v = *(float4*)&sY[d * PY + q * 4];
        __stcs((float4*)(outp + (size_t)d * N_WORLDS + q * 4), v);
    }
}

// ---------------------------------------------------------------------------
extern "C" void kernel_launch(void* const* d_in, const int* in_sizes, int n_in,
                              void* d_out, int out_size) {
    (void)in_sizes; (void)n_in; (void)out_size;
    const float* worlds  = (const float*)d_in[0];   // (2048, 64) f32
    const float* W       = (const float*)d_in[1];   // (512, 64, 64) f32
    const int*   nullary = (const int*)d_in[2];     // (1024, 2) i32
    float*       out     = (float*)d_out;           // (1024, 64, 2048) f32

    cudaFuncSetAttribute(nullary_kernel,
                         cudaFuncAttributeMaxDynamicSharedMemorySize,
                         SMEM_BYTES);

    bin_kernel<<<1, BATCH>>>(nullary);
    nullary_kernel<<<dim3(NTILES, BATCH), THREADS, SMEM_BYTES>>>(worlds, W, out);
}